// round 13
// baseline (speedup 1.0000x reference)
#include <cuda_runtime.h>
#include <cuda_bf16.h>
#include <cstdint>

#define B 4
#define L 512
#define D 128
#define QT 16            // queries per block
#define EPSV 1e-8f

// ---- smem carve (byte offsets) ----
// BHI/BLO: k-major [d=128][n=256] bf16, 512 B/row, 16B-chunk swizzle cn^(d&7)
#define OFF_BHI 0
#define OFF_BLO 65536
#define OFF_AHI 131072            // [32 r][256 B]  (swizzled, rows 0..17 used)
#define OFF_ALO 139264
#define OFF_XS  147456            // fp32 [18][128]
#define OFF_C   156672            // fp32 [32][260]
#define SMEM_BYTES 189952
#define CSTRIDE 260

__device__ __forceinline__ unsigned smem_u32(const void* p) {
    return (unsigned)__cvta_generic_to_shared(p);
}
__device__ __forceinline__ void ldsm_x4(unsigned* r, unsigned addr) {
    asm volatile("ldmatrix.sync.aligned.m8n8.x4.shared.b16 {%0,%1,%2,%3}, [%4];"
                 : "=r"(r[0]), "=r"(r[1]), "=r"(r[2]), "=r"(r[3]) : "r"(addr));
}
__device__ __forceinline__ void ldsm_x2_trans(unsigned& r0, unsigned& r1, unsigned addr) {
    asm volatile("ldmatrix.sync.aligned.m8n8.x2.trans.shared.b16 {%0,%1}, [%2];"
                 : "=r"(r0), "=r"(r1) : "r"(addr));
}
__device__ __forceinline__ void mma_bf16(float* c, const unsigned* a,
                                         unsigned b0, unsigned b1) {
    asm volatile(
        "mma.sync.aligned.m16n8k16.row.col.f32.bf16.bf16.f32 "
        "{%0,%1,%2,%3}, {%4,%5,%6,%7}, {%8,%9}, {%0,%1,%2,%3};"
        : "+f"(c[0]), "+f"(c[1]), "+f"(c[2]), "+f"(c[3])
        : "r"(a[0]), "r"(a[1]), "r"(a[2]), "r"(a[3]), "r"(b0), "r"(b1));
}

// accurate tanh: 1 - 2/(e^{2x}+1)
__device__ __forceinline__ float tanh_acc(float x) {
    float e2 = __expf(2.0f * x);
    return 1.0f - __fdividef(2.0f, e2 + 1.0f);
}

// split one fp32 into bf16 hi/lo (packed ushort)
__device__ __forceinline__ void bf_split(float v, unsigned short& h, unsigned short& l) {
    __nv_bfloat16 hb = __float2bfloat16_rn(v);
    h = __bfloat16_as_ushort(hb);
    l = __bfloat16_as_ushort(__float2bfloat16_rn(v - __bfloat162float(hb)));
}

// ---------------------------------------------------------------------------
// Single fused kernel. grid (L/QT, B) = (32, 4) = 128 blocks; 512 threads.
// C[32x256] = Atile(bf16 split, rows X[q0-1..q0+16]) @ [Wt|Wx](bf16 split).
// q row r = C[r+1][0:128], k tile row r = C[r][128:256]. Window softmax + out.
// ---------------------------------------------------------------------------
__global__ __launch_bounds__(512, 1) void fused_kernel(
    const float* __restrict__ X,  const float* __restrict__ Wt,
    const float* __restrict__ Wx, const float* __restrict__ Wa,
    const float* __restrict__ bh, const float* __restrict__ ba_p,
    float* __restrict__ out)
{
    extern __shared__ char smem[];
    char* BHI = smem + OFF_BHI;
    char* BLO = smem + OFF_BLO;
    char* AHI = smem + OFF_AHI;
    char* ALO = smem + OFF_ALO;
    float* Xs = (float*)(smem + OFF_XS);
    float* Cs = (float*)(smem + OFF_C);

    const int b    = blockIdx.y;
    const int q0   = blockIdx.x * QT;
    const int tid  = threadIdx.x;
    const int wid  = tid >> 5;
    const int lane = tid & 31;
    const float* XB = X + b * L * D;

    // ---- issue all weight LDGs first (16 x LDG.128 per thread, in flight) ----
    float4 wv[16];
    #pragma unroll
    for (int j = 0; j < 16; j++) {
        int f   = j * 512 + tid;           // 0..8191 float4 index
        int mat = f >> 12;                 // 0 = Wt, 1 = Wx
        int m   = f & 4095;
        wv[j] = ((const float4*)(mat ? Wx : Wt))[m];
    }

    // ---- A tile: 18 rows fp32 + bf16 hi/lo (swizzled); 576 items, 512 thr ----
    for (int i = tid; i < 18 * 32; i += 512) {
        int r  = i >> 5;                   // tile row 0..17
        int d4 = i & 31;
        int row = min(max(q0 - 1 + r, 0), L - 1);
        float4 v = ((const float4*)(XB + row * D))[d4];
        ((float4*)(Xs + r * D))[d4] = v;

        unsigned short hx, lx, hy, ly, hz, lz, hw, lw;
        bf_split(v.x, hx, lx); bf_split(v.y, hy, ly);
        bf_split(v.z, hz, lz); bf_split(v.w, hw, lw);

        int off = r * 256 + (((d4 >> 1) ^ (r & 7)) << 4) + ((d4 & 1) << 3);
        *(uint2*)(AHI + off) = make_uint2((unsigned)hx | ((unsigned)hy << 16),
                                          (unsigned)hz | ((unsigned)hw << 16));
        *(uint2*)(ALO + off) = make_uint2((unsigned)lx | ((unsigned)ly << 16),
                                          (unsigned)lz | ((unsigned)lw << 16));
    }

    // ---- convert + store weights to k-major swizzled smem ----
    #pragma unroll
    for (int j = 0; j < 16; j++) {
        int f   = j * 512 + tid;
        int mat = f >> 12;
        int m   = f & 4095;
        int d   = m >> 5;                  // 0..127
        int n4  = m & 31;
        int nn  = mat * 128 + n4 * 4;      // global col 0..255
        float4 v = wv[j];

        unsigned short hx, lx, hy, ly, hz, lz, hw, lw;
        bf_split(v.x, hx, lx); bf_split(v.y, hy, ly);
        bf_split(v.z, hz, lz); bf_split(v.w, hw, lw);

        int cn  = nn >> 3;
        int off = d * 512 + ((cn ^ (d & 7)) << 4) + ((nn & 7) * 2);
        *(uint2*)(BHI + off) = make_uint2((unsigned)hx | ((unsigned)hy << 16),
                                          (unsigned)hz | ((unsigned)hw << 16));
        *(uint2*)(BLO + off) = make_uint2((unsigned)lx | ((unsigned)ly << 16),
                                          (unsigned)lz | ((unsigned)lw << 16));
    }
    __syncthreads();

    // ---- HMMA GEMM: warp = (mtile, 32-col group) ----
    const int m0 = (wid >> 3) * 16;        // 0 or 16
    const int n0 = (wid & 7) * 32;

    float cfr[4][4];
    #pragma unroll
    for (int nt = 0; nt < 4; nt++)
        #pragma unroll
        for (int j = 0; j < 4; j++) cfr[nt][j] = 0.f;

    const int qd   = lane >> 3;            // A quadrant
    const int arow = m0 + ((qd & 1) << 3) + (lane & 7);
    const int bk   = lane & 15;            // B k-row provider within k16
    const int cn0  = n0 >> 3;

    #pragma unroll
    for (int kk = 0; kk < 8; kk++) {
        const int kc = kk * 2;             // A 16B-chunk base for this k16
        unsigned ahi[4], alo[4];
        {
            int ac = (kc + (qd >> 1)) ^ (arow & 7);
            ldsm_x4(ahi, smem_u32(AHI + arow * 256 + (ac << 4)));
            ldsm_x4(alo, smem_u32(ALO + arow * 256 + (ac << 4)));
        }
        const int dB  = kk * 16 + bk;      // B k-row for this lane
        const int brow = dB * 512;
        const int bsw  = dB & 7;
        #pragma unroll
        for (int nt = 0; nt < 4; nt++) {
            int bc = (cn0 + nt) ^ bsw;
            unsigned bh0, bh1, bl0, bl1;
            ldsm_x2_trans(bh0, bh1, smem_u32(BHI + brow + (bc << 4)));
            ldsm_x2_trans(bl0, bl1, smem_u32(BLO + brow + (bc << 4)));
            mma_bf16(cfr[nt], ahi, bh0, bh1);
            mma_bf16(cfr[nt], ahi, bl0, bl1);
            mma_bf16(cfr[nt], alo, bh0, bh1);
        }
    }

    // ---- epilogue: c-frags -> Cs[32][260] ----
    {
        int r0 = m0 + (lane >> 2);
        int r1 = r0 + 8;
        int c0 = (lane & 3) * 2;
        #pragma unroll
        for (int nt = 0; nt < 4; nt++) {
            int col = n0 + nt * 8 + c0;
            *(float2*)&Cs[r0 * CSTRIDE + col] = make_float2(cfr[nt][0], cfr[nt][1]);
            *(float2*)&Cs[r1 * CSTRIDE + col] = make_float2(cfr[nt][2], cfr[nt][3]);
        }
    }
    __syncthreads();

    // ---- window phase: 16 warps, warp == query ----
    const int rq = wid;                    // 0..15
    const int qi = q0 + rq;

    float4 qv  = *(const float4*)&Cs[(rq + 1) * CSTRIDE + lane * 4];   // q part
    float4 bhv = ((const float4*)bh)[lane];
    qv.x += bhv.x; qv.y += bhv.y; qv.z += bhv.z; qv.w += bhv.w;
    const float4 wvv = ((const float4*)Wa)[lane];
    const float bav = ba_p[0];

    float e[3];
    #pragma unroll
    for (int tt = 0; tt < 3; tt++) {
        int j = qi - 1 + tt;                                // global key
        float4 kv = *(const float4*)&Cs[(rq + tt) * CSTRIDE + 128 + lane * 4];
        float p = tanh_acc(qv.x + kv.x) * wvv.x
                + tanh_acc(qv.y + kv.y) * wvv.y
                + tanh_acc(qv.z + kv.z) * wvv.z
                + tanh_acc(qv.w + kv.w) * wvv.w;
        #pragma unroll
        for (int o = 16; o > 0; o >>= 1)
            p += __shfl_xor_sync(0xffffffffu, p, o);
        e[tt] = (j >= 0 && j < L) ? (p + bav) : -1e30f;
    }

    float m  = fmaxf(e[0], fmaxf(e[1], e[2]));
    float w0 = __expf(e[0] - m);
    float w1 = __expf(e[1] - m);
    float w2 = __expf(e[2] - m);
    float inv = __fdividef(1.0f, w0 + w1 + w2 + EPSV);

    float4 o4 = make_float4(0.f, 0.f, 0.f, 0.f);
    #pragma unroll
    for (int tt = 0; tt < 3; tt++) {
        float w = (tt == 0) ? w0 : (tt == 1) ? w1 : w2;
        float a = w * inv;
        float4 xv = ((const float4*)(Xs + (rq + tt) * D))[lane];
        o4.x = fmaf(a, xv.x, o4.x);
        o4.y = fmaf(a, xv.y, o4.y);
        o4.z = fmaf(a, xv.z, o4.z);
        o4.w = fmaf(a, xv.w, o4.w);
    }
    ((float4*)(out + (b * L + qi) * D))[lane] = o4;
}

extern "C" void kernel_launch(void* const* d_in, const int* in_sizes, int n_in,
                              void* d_out, int out_size)
{
    const float* X  = (const float*)d_in[0];
    const float* Wt = (const float*)d_in[1];
    const float* Wx = (const float*)d_in[2];
    const float* Wa = (const float*)d_in[3];
    const float* bh = (const float*)d_in[4];
    const float* ba = (const float*)d_in[5];
    float* out = (float*)d_out;

    cudaFuncSetAttribute(fused_kernel,
                         cudaFuncAttributeMaxDynamicSharedMemorySize, SMEM_BYTES);
    dim3 grid(L / QT, B);
    fused_kernel<<<grid, 512, SMEM_BYTES>>>(X, Wt, Wx, Wa, bh, ba, out);
}

// round 14
// speedup vs baseline: 1.1698x; 1.1698x over previous
#include <cuda_runtime.h>
#include <cuda_bf16.h>
#include <cstdint>

#define B 4
#define L 512
#define D 128
#define QT 16            // queries per block
#define EPSV 1e-8f

// prebuilt swizzled smem images of [Wt|Wx] in bf16 hi/lo, k-major [d][n]
__device__ __align__(16) unsigned char g_BHIimg[65536];
__device__ __align__(16) unsigned char g_BLOimg[65536];

// ---- smem carve (byte offsets) ----
// BHI/BLO: k-major [d=128][n=256] bf16, 512 B/row, 16B-chunk swizzle cn^(d&7)
#define OFF_BHI 0
#define OFF_BLO 65536
#define OFF_AHI 131072            // [32 r][256 B]  (swizzled, rows 0..17 used)
#define OFF_ALO 139264
#define OFF_XS  147456            // fp32 [18][128]
#define OFF_C   156672            // fp32 [32][260]
#define OFF_MBAR 189952
#define SMEM_BYTES 189984
#define CSTRIDE 260

__device__ __forceinline__ unsigned smem_u32(const void* p) {
    return (unsigned)__cvta_generic_to_shared(p);
}
__device__ __forceinline__ void ldsm_x4(unsigned* r, unsigned addr) {
    asm volatile("ldmatrix.sync.aligned.m8n8.x4.shared.b16 {%0,%1,%2,%3}, [%4];"
                 : "=r"(r[0]), "=r"(r[1]), "=r"(r[2]), "=r"(r[3]) : "r"(addr));
}
__device__ __forceinline__ void ldsm_x2_trans(unsigned& r0, unsigned& r1, unsigned addr) {
    asm volatile("ldmatrix.sync.aligned.m8n8.x2.trans.shared.b16 {%0,%1}, [%2];"
                 : "=r"(r0), "=r"(r1) : "r"(addr));
}
__device__ __forceinline__ void mma_bf16(float* c, const unsigned* a,
                                         unsigned b0, unsigned b1) {
    asm volatile(
        "mma.sync.aligned.m16n8k16.row.col.f32.bf16.bf16.f32 "
        "{%0,%1,%2,%3}, {%4,%5,%6,%7}, {%8,%9}, {%0,%1,%2,%3};"
        : "+f"(c[0]), "+f"(c[1]), "+f"(c[2]), "+f"(c[3])
        : "r"(a[0]), "r"(a[1]), "r"(a[2]), "r"(a[3]), "r"(b0), "r"(b1));
}

__device__ __forceinline__ void bulk_copy(void* dst_smem, const void* src_gmem,
                                          unsigned bytes, unsigned mbar) {
    asm volatile(
        "cp.async.bulk.shared::cluster.global.mbarrier::complete_tx::bytes "
        "[%0], [%1], %2, [%3];"
        :: "r"(smem_u32(dst_smem)), "l"(src_gmem), "r"(bytes), "r"(mbar)
        : "memory");
}

// accurate tanh: 1 - 2/(e^{2x}+1)
__device__ __forceinline__ float tanh_acc(float x) {
    float e2 = __expf(2.0f * x);
    return 1.0f - __fdividef(2.0f, e2 + 1.0f);
}

// split one fp32 into bf16 hi/lo (packed ushort)
__device__ __forceinline__ void bf_split(float v, unsigned short& h, unsigned short& l) {
    __nv_bfloat16 hb = __float2bfloat16_rn(v);
    h = __bfloat16_as_ushort(hb);
    l = __bfloat16_as_ushort(__float2bfloat16_rn(v - __bfloat162float(hb)));
}

// ---------------------------------------------------------------------------
// prep: build swizzled smem images of [Wt|Wx] bf16 hi/lo in global memory.
// grid 16 blocks x 512 threads; thread = one float4 of source weight.
// ---------------------------------------------------------------------------
__global__ __launch_bounds__(512) void prep_kernel(
    const float* __restrict__ Wt, const float* __restrict__ Wx)
{
    int f   = blockIdx.x * 512 + threadIdx.x;  // 0..8191
    int mat = f >> 12;                         // 0 = Wt, 1 = Wx
    int m   = f & 4095;
    float4 v = ((const float4*)(mat ? Wx : Wt))[m];

    int d  = m >> 5;                           // 0..127
    int nn = mat * 128 + (m & 31) * 4;         // global col 0..255

    unsigned short hx, lx, hy, ly, hz, lz, hw, lw;
    bf_split(v.x, hx, lx); bf_split(v.y, hy, ly);
    bf_split(v.z, hz, lz); bf_split(v.w, hw, lw);

    int cn  = nn >> 3;
    int off = d * 512 + ((cn ^ (d & 7)) << 4) + ((nn & 7) * 2);
    *(uint2*)(g_BHIimg + off) = make_uint2((unsigned)hx | ((unsigned)hy << 16),
                                           (unsigned)hz | ((unsigned)hw << 16));
    *(uint2*)(g_BLOimg + off) = make_uint2((unsigned)lx | ((unsigned)ly << 16),
                                           (unsigned)lz | ((unsigned)lw << 16));
}

// ---------------------------------------------------------------------------
// main: grid (L/QT, B) = (32, 4) = 128 blocks; 512 threads (16 warps).
// B staged via cp.async.bulk from prebuilt images. HMMA 3-term bf16 split.
// ---------------------------------------------------------------------------
__global__ __launch_bounds__(512, 1) void fused_kernel(
    const float* __restrict__ X,  const float* __restrict__ Wa,
    const float* __restrict__ bh, const float* __restrict__ ba_p,
    float* __restrict__ out)
{
    extern __shared__ char smem[];
    char* BHI = smem + OFF_BHI;
    char* BLO = smem + OFF_BLO;
    char* AHI = smem + OFF_AHI;
    char* ALO = smem + OFF_ALO;
    float* Xs = (float*)(smem + OFF_XS);
    float* Cs = (float*)(smem + OFF_C);
    const unsigned mbar = smem_u32(smem + OFF_MBAR);

    const int b    = blockIdx.y;
    const int q0   = blockIdx.x * QT;
    const int tid  = threadIdx.x;
    const int wid  = tid >> 5;
    const int lane = tid & 31;
    const float* XB = X + b * L * D;

    // ---- mbarrier init, then launch bulk copies of the weight images ----
    if (tid == 0) {
        asm volatile("mbarrier.init.shared.b64 [%0], 1;" :: "r"(mbar) : "memory");
    }
    __syncthreads();
    if (tid == 0) {
        asm volatile("mbarrier.arrive.expect_tx.shared.b64 _, [%0], %1;"
                     :: "r"(mbar), "r"(131072u) : "memory");
        #pragma unroll
        for (int i = 0; i < 4; i++) {
            bulk_copy(BHI + i * 16384, g_BHIimg + i * 16384, 16384u, mbar);
            bulk_copy(BLO + i * 16384, g_BLOimg + i * 16384, 16384u, mbar);
        }
    }

    // ---- A tile: 18 rows fp32 + bf16 hi/lo (swizzled); 576 items, 512 thr ----
    for (int i = tid; i < 18 * 32; i += 512) {
        int r  = i >> 5;                   // tile row 0..17
        int d4 = i & 31;
        int row = min(max(q0 - 1 + r, 0), L - 1);
        float4 v = ((const float4*)(XB + row * D))[d4];
        ((float4*)(Xs + r * D))[d4] = v;

        unsigned short hx, lx, hy, ly, hz, lz, hw, lw;
        bf_split(v.x, hx, lx); bf_split(v.y, hy, ly);
        bf_split(v.z, hz, lz); bf_split(v.w, hw, lw);

        int off = r * 256 + (((d4 >> 1) ^ (r & 7)) << 4) + ((d4 & 1) << 3);
        *(uint2*)(AHI + off) = make_uint2((unsigned)hx | ((unsigned)hy << 16),
                                          (unsigned)hz | ((unsigned)hw << 16));
        *(uint2*)(ALO + off) = make_uint2((unsigned)lx | ((unsigned)ly << 16),
                                          (unsigned)lz | ((unsigned)lw << 16));
    }

    // ---- wait for bulk copies, then block-wide barrier for A tile ----
    {
        unsigned done = 0;
        while (!done) {
            asm volatile(
                "{\n\t.reg .pred p;\n\t"
                "mbarrier.try_wait.parity.acquire.cta.shared::cta.b64 p, [%1], %2, 0x989680;\n\t"
                "selp.b32 %0, 1, 0, p;\n\t}"
                : "=r"(done) : "r"(mbar), "r"(0u) : "memory");
        }
    }
    __syncthreads();

    // ---- HMMA GEMM: warp = (mtile, 32-col group) ----
    const int m0 = (wid >> 3) * 16;        // 0 or 16
    const int n0 = (wid & 7) * 32;

    float cfr[4][4];
    #pragma unroll
    for (int nt = 0; nt < 4; nt++)
        #pragma unroll
        for (int j = 0; j < 4; j++) cfr[nt][j] = 0.f;

    const int qd   = lane >> 3;            // A quadrant
    const int arow = m0 + ((qd & 1) << 3) + (lane & 7);
    const int bk   = lane & 15;            // B k-row provider within k16
    const int cn0  = n0 >> 3;

    #pragma unroll
    for (int kk = 0; kk < 8; kk++) {
        const int kc = kk * 2;             // A 16B-chunk base for this k16
        unsigned ahi[4], alo[4];
        {
            int ac = (kc + (qd >> 1)) ^ (arow & 7);
            ldsm_x4(ahi, smem_u32(AHI + arow * 256 + (ac << 4)));
            ldsm_x4(alo, smem_u32(ALO + arow * 256 + (ac << 4)));
        }
        const int dB   = kk * 16 + bk;     // B k-row for this lane
        const int brow = dB * 512;
        const int bsw  = dB & 7;
        #pragma unroll
        for (int nt = 0; nt < 4; nt++) {
            int bc = (cn0 + nt) ^ bsw;
            unsigned bh0, bh1, bl0, bl1;
            ldsm_x2_trans(bh0, bh1, smem_u32(BHI + brow + (bc << 4)));
            ldsm_x2_trans(bl0, bl1, smem_u32(BLO + brow + (bc << 4)));
            mma_bf16(cfr[nt], ahi, bh0, bh1);
            mma_bf16(cfr[nt], ahi, bl0, bl1);
            mma_bf16(cfr[nt], alo, bh0, bh1);
        }
    }

    // ---- epilogue: c-frags -> Cs[32][260] ----
    {
        int r0 = m0 + (lane >> 2);
        int r1 = r0 + 8;
        int c0 = (lane & 3) * 2;
        #pragma unroll
        for (int nt = 0; nt < 4; nt++) {
            int col = n0 + nt * 8 + c0;
            *(float2*)&Cs[r0 * CSTRIDE + col] = make_float2(cfr[nt][0], cfr[nt][1]);
            *(float2*)&Cs[r1 * CSTRIDE + col] = make_float2(cfr[nt][2], cfr[nt][3]);
        }
    }
    __syncthreads();

    // ---- window phase: 16 warps, warp == query ----
    const int rq = wid;                    // 0..15
    const int qi = q0 + rq;

    float4 qv  = *(const float4*)&Cs[(rq + 1) * CSTRIDE + lane * 4];   // q part
    float4 bhv = ((const float4*)bh)[lane];
    qv.x += bhv.x; qv.y += bhv.y; qv.z += bhv.z; qv.w += bhv.w;
    const float4 wvv = ((const float4*)Wa)[lane];
    const float bav = ba_p[0];

    float e[3];
    #pragma unroll
    for (int tt = 0; tt < 3; tt++) {
        int j = qi - 1 + tt;                                // global key
        float4 kv = *(const float4*)&Cs[(rq + tt) * CSTRIDE + 128 + lane * 4];
        float p = tanh_acc(qv.x + kv.x) * wvv.x
                + tanh_acc(qv.y + kv.y) * wvv.y
                + tanh_acc(qv.z + kv.z) * wvv.z
                + tanh_acc(qv.w + kv.w) * wvv.w;
        #pragma unroll
        for (int o = 16; o > 0; o >>= 1)
            p += __shfl_xor_sync(0xffffffffu, p, o);
        e[tt] = (j >= 0 && j < L) ? (p + bav) : -1e30f;
    }

    float m  = fmaxf(e[0], fmaxf(e[1], e[2]));
    float w0 = __expf(e[0] - m);
    float w1 = __expf(e[1] - m);
    float w2 = __expf(e[2] - m);
    float inv = __fdividef(1.0f, w0 + w1 + w2 + EPSV);

    float4 o4 = make_float4(0.f, 0.f, 0.f, 0.f);
    #pragma unroll
    for (int tt = 0; tt < 3; tt++) {
        float w = (tt == 0) ? w0 : (tt == 1) ? w1 : w2;
        float a = w * inv;
        float4 xv = ((const float4*)(Xs + (rq + tt) * D))[lane];
        o4.x = fmaf(a, xv.x, o4.x);
        o4.y = fmaf(a, xv.y, o4.y);
        o4.z = fmaf(a, xv.z, o4.z);
        o4.w = fmaf(a, xv.w, o4.w);
    }
    ((float4*)(out + (b * L + qi) * D))[lane] = o4;
}

extern "C" void kernel_launch(void* const* d_in, const int* in_sizes, int n_in,
                              void* d_out, int out_size)
{
    const float* X  = (const float*)d_in[0];
    const float* Wt = (const float*)d_in[1];
    const float* Wx = (const float*)d_in[2];
    const float* Wa = (const float*)d_in[3];
    const float* bh = (const float*)d_in[4];
    const float* ba = (const float*)d_in[5];
    float* out = (float*)d_out;

    prep_kernel<<<16, 512>>>(Wt, Wx);

    cudaFuncSetAttribute(fused_kernel,
                         cudaFuncAttributeMaxDynamicSharedMemorySize, SMEM_BYTES);
    dim3 grid(L / QT, B);
    fused_kernel<<<grid, 512, SMEM_BYTES>>>(X, Wa, bh, ba, out);
}